// round 7
// baseline (speedup 1.0000x reference)
#include <cuda_runtime.h>

#define NN 50000
#define NE 800000
#define ENC 64
#define OUTD 5

// ---------------- scratch (static __device__ — no allocations allowed) ----------------
__device__ float g_h0[NN * ENC];
__device__ float g_hA[NN * ENC];
__device__ float g_hB[NN * ENC];
__device__ float g_xl[NN * ENC];
__device__ float g_xr[NN * ENC];
__device__ float g_s[NE];
__device__ int   g_counts[NN];
__device__ int   g_rowptr[NN + 1];
__device__ int   g_offs[NN];
__device__ int   g_eids[NE];
__device__ float g_Weff[6 * 4 * ENC];   // per (stack,round): W_edge @ We  [4,64]
__device__ float g_beff[6 * ENC];       // per (stack,round): b_edge @ We  [64]

// ---------------- packed f32x2 helpers (sm_103a FFMA2) ----------------
__device__ __forceinline__ unsigned long long pack2(float h) {
    unsigned long long r;
    asm("mov.b64 %0, {%1, %1};" : "=l"(r) : "f"(h));
    return r;
}
__device__ __forceinline__ void fma2(unsigned long long& acc, unsigned long long w,
                                     unsigned long long h) {
    asm("fma.rn.f32x2 %0, %1, %2, %0;" : "+l"(acc) : "l"(w), "l"(h));
}

// ---------------- CSR build ----------------
__global__ void k_zero_counts() {
    int i = blockIdx.x * blockDim.x + threadIdx.x;
    if (i < NN) g_counts[i] = 0;
}

__global__ void k_count(const int* __restrict__ dst) {
    int e = blockIdx.x * blockDim.x + threadIdx.x;
    if (e < NE) atomicAdd(&g_counts[dst[e]], 1);
}

// single block, 1024 threads: exclusive scan of counts -> rowptr (+ copy to offs)
__global__ void k_scan() {
    __shared__ int swarp[32];
    int tid = threadIdx.x, lane = tid & 31, wid = tid >> 5;
    int base = 0;
    for (int start = 0; start < NN; start += 1024) {
        int i = start + tid;
        int c = (i < NN) ? g_counts[i] : 0;
        int v = c;
#pragma unroll
        for (int d = 1; d < 32; d <<= 1) {
            int t = __shfl_up_sync(0xffffffffu, v, d);
            if (lane >= d) v += t;
        }
        if (lane == 31) swarp[wid] = v;
        __syncthreads();
        if (wid == 0) {
            int wv = swarp[lane];
#pragma unroll
            for (int d = 1; d < 32; d <<= 1) {
                int t = __shfl_up_sync(0xffffffffu, wv, d);
                if (lane >= d) wv += t;
            }
            swarp[lane] = wv;
        }
        __syncthreads();
        int prefix = (wid == 0) ? 0 : swarp[wid - 1];
        int excl = base + prefix + v - c;
        if (i < NN) { g_rowptr[i] = excl; g_offs[i] = excl; }
        int tot = swarp[31];
        __syncthreads();   // protect swarp before next iteration overwrites
        base += tot;
    }
    if (tid == 0) g_rowptr[NN] = base;
}

__global__ void k_scatter(const int* __restrict__ dst) {
    int e = blockIdx.x * blockDim.x + threadIdx.x;
    if (e < NE) {
        int p = atomicAdd(&g_offs[dst[e]], 1);
        g_eids[p] = e;
    }
}

// ---------------- edge-weight folding: Weff = W_edge @ We, beff = b_edge @ We ----------------
__global__ void k_weff(const float* __restrict__ W_edge, const float* __restrict__ b_edge,
                       const float* __restrict__ aWe, const float* __restrict__ cWe) {
    int b = blockIdx.x;          // 0..5 : stack*3 + round
    int k = threadIdx.x;         // 0..63
    const float* We = (b < 3) ? (aWe + b * ENC * ENC) : (cWe + (b - 3) * ENC * ENC);
#pragma unroll
    for (int j = 0; j < 4; j++) {
        float acc = 0.f;
        for (int m = 0; m < ENC; m++) acc = fmaf(W_edge[j * ENC + m], We[m * ENC + k], acc);
        g_Weff[b * 4 * ENC + j * ENC + k] = acc;
    }
    float bb = 0.f;
    for (int m = 0; m < ENC; m++) bb = fmaf(b_edge[m], We[m * ENC + k], bb);
    g_beff[b * ENC + k] = bb;
}

// ---------------- node encoder: h0 = x @ W_node + b_node ----------------
__global__ void k_node_enc(const float* __restrict__ x, const float* __restrict__ Wn,
                           const float* __restrict__ bn) {
    __shared__ float sW[8 * ENC];
    __shared__ float sb[ENC];
    int tid = threadIdx.x;
    for (int i = tid; i < 8 * ENC; i += blockDim.x) sW[i] = Wn[i];
    for (int i = tid; i < ENC; i += blockDim.x) sb[i] = bn[i];
    __syncthreads();
    int n = blockIdx.x * blockDim.x + tid;
    if (n >= NN) return;
    float xv[8];
#pragma unroll
    for (int j = 0; j < 8; j++) xv[j] = x[n * 8 + j];
    for (int k = 0; k < ENC; k++) {
        float acc = sb[k];
#pragma unroll
        for (int j = 0; j < 8; j++) acc = fmaf(xv[j], sW[j * ENC + k], acc);
        g_h0[n * ENC + k] = acc;
    }
}

// ---------------- fused xl/xr GEMM: xl = h@Wl, xr = h@Wr (f32x2 packed FMA) ----------------
// block = 256 threads (tx 0..15 -> dim pairs, ty 0..15 -> 4 nodes each), 64-node tile
__global__ __launch_bounds__(256) void k_gemm(int in_sel,
                                              const float* __restrict__ Wl,
                                              const float* __restrict__ Wr) {
    __shared__ float sWl[ENC * ENC];
    __shared__ float sWr[ENC * ENC];
    __shared__ float sH[64 * ENC];
    const float* h = (in_sel == 0) ? g_h0 : ((in_sel == 1) ? g_hA : g_hB);
    int tid = threadIdx.x;
    int tx = tid & 15, ty = tid >> 4;
    int n0 = blockIdx.x * 64;
    for (int i = tid; i < ENC * ENC; i += 256) { sWl[i] = Wl[i]; sWr[i] = Wr[i]; }
    for (int i = tid; i < 64 * ENC; i += 256) {
        int n = n0 + (i >> 6);
        sH[i] = (n < NN) ? h[n0 * ENC + i] : 0.f;
    }
    __syncthreads();

    unsigned long long al0[4], al1[4], ar0[4], ar1[4];
#pragma unroll
    for (int i = 0; i < 4; i++) { al0[i] = 0ull; al1[i] = 0ull; ar0[i] = 0ull; ar1[i] = 0ull; }

#pragma unroll 4
    for (int j = 0; j < ENC; j++) {
        unsigned long long wl0 = *(const unsigned long long*)&sWl[j * ENC + 2 * tx];
        unsigned long long wl1 = *(const unsigned long long*)&sWl[j * ENC + 32 + 2 * tx];
        unsigned long long wr0 = *(const unsigned long long*)&sWr[j * ENC + 2 * tx];
        unsigned long long wr1 = *(const unsigned long long*)&sWr[j * ENC + 32 + 2 * tx];
#pragma unroll
        for (int i = 0; i < 4; i++) {
            unsigned long long hp = pack2(sH[(ty + 16 * i) * ENC + j]);
            fma2(al0[i], wl0, hp);
            fma2(al1[i], wl1, hp);
            fma2(ar0[i], wr0, hp);
            fma2(ar1[i], wr1, hp);
        }
    }
#pragma unroll
    for (int i = 0; i < 4; i++) {
        int n = n0 + ty + 16 * i;
        if (n < NN) {
            *(unsigned long long*)&g_xl[n * ENC + 2 * tx]      = al0[i];
            *(unsigned long long*)&g_xl[n * ENC + 32 + 2 * tx] = al1[i];
            *(unsigned long long*)&g_xr[n * ENC + 2 * tx]      = ar0[i];
            *(unsigned long long*)&g_xr[n * ENC + 32 + 2 * tx] = ar1[i];
        }
    }
}

// ---------------- edge scoring: s[e] = leaky_relu(xl[src]+xr[dst]+ep) . att ----------------
// 8 lanes per edge; Weff/att/beff slices preloaded to registers
__global__ __launch_bounds__(256) void k_score(const float* __restrict__ ea,
                                               const int* __restrict__ src,
                                               const int* __restrict__ dst,
                                               int widx, const float* __restrict__ att) {
    int gt = blockIdx.x * blockDim.x + threadIdx.x;
    int ln8 = gt & 7;
    int grp = gt >> 3;
    int ngroups = (gridDim.x * blockDim.x) >> 3;
    int d0 = ln8 * 8;

    float w0[8], w1[8], w2[8], w3[8], a8[8], be8[8];
    const float* Weff = &g_Weff[widx * 4 * ENC];
    const float* beff = &g_beff[widx * ENC];
#pragma unroll
    for (int t = 0; t < 8; t++) {
        w0[t] = Weff[0 * ENC + d0 + t];
        w1[t] = Weff[1 * ENC + d0 + t];
        w2[t] = Weff[2 * ENC + d0 + t];
        w3[t] = Weff[3 * ENC + d0 + t];
        a8[t] = att[d0 + t];
        be8[t] = beff[d0 + t];
    }

    for (int e = grp; e < NE; e += ngroups) {
        int si = __ldg(&src[e]);
        int di = __ldg(&dst[e]);
        float4 xa = *(const float4*)&g_xl[si * ENC + d0];
        float4 xb = *(const float4*)&g_xl[si * ENC + d0 + 4];
        float4 ra = *(const float4*)&g_xr[di * ENC + d0];
        float4 rb = *(const float4*)&g_xr[di * ENC + d0 + 4];
        float4 ev = *(const float4*)&ea[e * 4];
        float xlv[8] = {xa.x, xa.y, xa.z, xa.w, xb.x, xb.y, xb.z, xb.w};
        float xrv[8] = {ra.x, ra.y, ra.z, ra.w, rb.x, rb.y, rb.z, rb.w};
        float part = 0.f;
#pragma unroll
        for (int t = 0; t < 8; t++) {
            float ep = be8[t];
            ep = fmaf(ev.x, w0[t], ep);
            ep = fmaf(ev.y, w1[t], ep);
            ep = fmaf(ev.z, w2[t], ep);
            ep = fmaf(ev.w, w3[t], ep);
            float m = xlv[t] + xrv[t] + ep;
            float lr = fmaxf(m, 0.f) + 0.2f * fminf(m, 0.f);
            part = fmaf(lr, a8[t], part);
        }
        part += __shfl_xor_sync(0xffffffffu, part, 4);
        part += __shfl_xor_sync(0xffffffffu, part, 2);
        part += __shfl_xor_sync(0xffffffffu, part, 1);
        if (ln8 == 0) g_s[e] = part;
    }
}

// ---------------- per-dst softmax + aggregation (warp per node, atomic-free) ----------------
// out[n] = (sum_e ex_e * xl[src_e]) / (sum_e ex_e) + bias ; optional relu
__global__ __launch_bounds__(256) void k_agg(const int* __restrict__ src,
                                             const float* __restrict__ bias,
                                             int out_sel, int do_relu) {
    int gw = (blockIdx.x * blockDim.x + threadIdx.x) >> 5;
    int lane = threadIdx.x & 31;
    if (gw >= NN) return;
    int node = gw;
    float* hout = (out_sel == 1) ? g_hA : g_hB;

    int beg = g_rowptr[node];
    int end = g_rowptr[node + 1];
    int deg = end - beg;

    float b0 = bias[2 * lane], b1 = bias[2 * lane + 1];
    float o0, o1;

    if (deg == 0) {
        o0 = b0; o1 = b1;
    } else {
        // pass A: segment max
        float mx = -3.0e38f;
        for (int j = lane; j < deg; j += 32) {
            int e = g_eids[beg + j];
            mx = fmaxf(mx, g_s[e]);
        }
#pragma unroll
        for (int d = 16; d; d >>= 1) mx = fmaxf(mx, __shfl_xor_sync(0xffffffffu, mx, d));

        // pass B: unnormalized weighted sum + denom, 32-edge chunks
        float denom = 0.f, acc0 = 0.f, acc1 = 0.f;
        for (int base = 0; base < deg; base += 32) {
            int j = base + lane;
            float ex = 0.f;
            int sj = 0;
            if (j < deg) {
                int e = g_eids[beg + j];
                ex = __expf(g_s[e] - mx);
                sj = __ldg(&src[e]);
            }
            denom += ex;
            int cnt = min(32, deg - base);
            for (int t = 0; t < cnt; t++) {
                float coef = __shfl_sync(0xffffffffu, ex, t);
                int srow = __shfl_sync(0xffffffffu, sj, t);
                float2 v = *(const float2*)&g_xl[srow * ENC + 2 * lane];
                acc0 = fmaf(coef, v.x, acc0);
                acc1 = fmaf(coef, v.y, acc1);
            }
        }
#pragma unroll
        for (int d = 16; d; d >>= 1) denom += __shfl_xor_sync(0xffffffffu, denom, d);
        float inv = 1.f / denom;
        o0 = fmaf(acc0, inv, b0);
        o1 = fmaf(acc1, inv, b1);
    }
    if (do_relu) { o0 = fmaxf(o0, 0.f); o1 = fmaxf(o1, 0.f); }
    float2 ov;
    ov.x = o0; ov.y = o1;
    *(float2*)&hout[node * ENC + 2 * lane] = ov;
}

// ---------------- decoders ----------------
__global__ void k_decode_act(const float* __restrict__ W, const float* __restrict__ b,
                             float* __restrict__ out) {
    __shared__ float sW[ENC * OUTD];
    __shared__ float sb[OUTD];
    int tid = threadIdx.x;
    for (int i = tid; i < ENC * OUTD; i += blockDim.x) sW[i] = W[i];
    if (tid < OUTD) sb[tid] = b[tid];
    __syncthreads();
    int n = blockIdx.x * blockDim.x + tid;
    if (n >= NN) return;
    float acc[OUTD];
#pragma unroll
    for (int c = 0; c < OUTD; c++) acc[c] = sb[c];
    const float* hr = &g_hA[n * ENC];
    for (int k = 0; k < ENC; k++) {
        float hv = hr[k];
#pragma unroll
        for (int c = 0; c < OUTD; c++) acc[c] = fmaf(hv, sW[k * OUTD + c], acc[c]);
    }
#pragma unroll
    for (int c = 0; c < OUTD; c++) out[n * 6 + c] = tanhf(acc[c]);
}

__global__ void k_decode_val(const float* __restrict__ W, const float* __restrict__ b,
                             float* __restrict__ out) {
    __shared__ float sW[ENC];
    __shared__ float sb0;
    int tid = threadIdx.x;
    for (int i = tid; i < ENC; i += blockDim.x) sW[i] = W[i];
    if (tid == 0) sb0 = b[0];
    __syncthreads();
    int n = blockIdx.x * blockDim.x + tid;
    if (n >= NN) return;
    float acc = sb0;
    const float* hr = &g_hB[0];  // placeholder silenced below
    (void)hr;
    const float* h = &g_hA[n * ENC];
    for (int k = 0; k < ENC; k++) acc = fmaf(h[k], sW[k], acc);
    out[n * 6 + 5] = acc;
}

// ---------------- launcher ----------------
extern "C" void kernel_launch(void* const* d_in, const int* in_sizes, int n_in,
                              void* d_out, int out_size) {
    const float* x      = (const float*)d_in[0];
    const float* ea     = (const float*)d_in[1];
    const float* W_node = (const float*)d_in[2];
    const float* b_node = (const float*)d_in[3];
    const float* W_edge = (const float*)d_in[4];
    const float* b_edge = (const float*)d_in[5];
    const float* aWl    = (const float*)d_in[6];
    const float* aWr    = (const float*)d_in[7];
    const float* aWe    = (const float*)d_in[8];
    const float* aatt   = (const float*)d_in[9];
    const float* ab     = (const float*)d_in[10];
    const float* cWl    = (const float*)d_in[11];
    const float* cWr    = (const float*)d_in[12];
    const float* cWe    = (const float*)d_in[13];
    const float* catt   = (const float*)d_in[14];
    const float* cb     = (const float*)d_in[15];
    const float* W_act  = (const float*)d_in[16];
    const float* b_act  = (const float*)d_in[17];
    const float* W_val  = (const float*)d_in[18];
    const float* b_val  = (const float*)d_in[19];
    const int*   src    = (const int*)d_in[20];
    const int*   dst    = (const int*)d_in[21];
    float* out = (float*)d_out;

    // CSR build (per call; atomics + single-block scan)
    k_zero_counts<<<(NN + 255) / 256, 256>>>();
    k_count<<<(NE + 255) / 256, 256>>>(dst);
    k_scan<<<1, 1024>>>();
    k_scatter<<<(NE + 255) / 256, 256>>>(dst);

    // folded edge weights + node encoder
    k_weff<<<6, ENC>>>(W_edge, b_edge, aWe, cWe);
    k_node_enc<<<(NN + 255) / 256, 256>>>(x, W_node, b_node);

    int gemm_blocks  = (NN + 63) / 64;
    int score_blocks = 1184;                     // 148 SMs * 8 blocks, grid-stride
    int agg_blocks   = (NN * 32 + 255) / 256;    // warp per node

    for (int s = 0; s < 2; s++) {
        const float* Wl  = s ? cWl : aWl;
        const float* Wr  = s ? cWr : aWr;
        const float* att = s ? catt : aatt;
        const float* bb  = s ? cb : ab;
        for (int r = 0; r < 3; r++) {
            int in_sel  = (r == 0) ? 0 : ((r == 1) ? 1 : 2);  // h0 -> hA -> hB
            int out_sel = (r == 1) ? 2 : 1;                   // hA, hB, hA
            k_gemm<<<gemm_blocks, 256>>>(in_sel, Wl + r * ENC * ENC, Wr + r * ENC * ENC);
            k_score<<<score_blocks, 256>>>(ea, src, dst, s * 3 + r, att + r * ENC);
            k_agg<<<agg_blocks, 256>>>(src, bb + r * ENC, out_sel, (r < 2) ? 1 : 0);
        }
        if (s == 0)
            k_decode_act<<<(NN + 255) / 256, 256>>>(W_act, b_act, out);
        else
            k_decode_val<<<(NN + 255) / 256, 256>>>(W_val, b_val, out);
    }
}